// round 17
// baseline (speedup 1.0000x reference)
#include <cuda_runtime.h>
#include <cstdint>

// RasterPoints — FINAL KERNEL.
// Best-measured configuration across 16 rounds: wall 106.8-107.1us,
// kernel 105.4-106.0us @ 88.2-88.7% DRAM (7.0 TB/s) — the pure-write-stream
// roofline of this GB300 part (write-turnaround bound; spec is 8 TB/s mixed).
//
// Output: [B=16, T=50, H=100, W=100, P=25] fp32 = 200M elems = 800MB, of
// which exactly B*T*P = 20000 elements are 1.0f.
//
// Design facts established experimentally:
//  * DRAM write BW is the only binding resource (issue 14%, ALU 8%, L2 63%).
//  * Store width (32/128/256-bit), cache policy (WB/.cs/.wt), and grid shape
//    are all neutral at saturation — the LTS/DRAM write path is
//    configuration-independent at its cap.
//  * SINGLE launch is mandatory: any second kernel costs >=4us.
//  * Per-CTA GLOBAL release fences serialize writeback: -181us. Persistent
//    grids with per-tile barriers lock-step the store stream: -11us.
//    -> free-running CTAs, CTA-scope ordering only.
//
// Algorithm: each of 48829 blocks owns one contiguous 4096-float slice.
//  Phase 2a (pre-barrier): compute the <=50 candidate 1.0f points of the
//    <=2 bt-regions (bt stride = H*W*P = 250000) overlapping the slice;
//    input loads hide under the store stream. Inputs only — no hazard.
//  Phase 1: zero the slice with 4x STG.128 evict-first streaming stores.
//  __syncthreads (CTA-scope zero->one ordering, ~7cyc).
//  Phase 2b: the single out[off]=1.0f for candidates inside the slice.
// Every output offset belongs to exactly one slice: exactly-once, race-free,
// deterministic, graph-capturable, allocation-free.

static constexpr int B = 16;
static constexpr int T = 50;
static constexpr int H = 100;
static constexpr int W = 100;
static constexpr int P = 25;
static constexpr unsigned BT_STRIDE = (unsigned)H * W * P;   // 250000

static constexpr int VPT = 4;                        // float4s per thread (64B)
static constexpr int ZTHREADS = 256;
static constexpr unsigned SLICE = ZTHREADS * VPT * 4;        // 4096 floats

__global__ void __launch_bounds__(ZTHREADS)
fused_raster_kernel(const float2* __restrict__ x,          // [B*T*P] (px,py)
                    const float2* __restrict__ resolution, // [B*T]
                    const float2* __restrict__ origin,     // [B*T]
                    float* __restrict__ out,
                    unsigned n_vec4) {
    // ---- Phase 2a (pre-barrier): candidate one-write for this slice ----
    const unsigned n = n_vec4 * 4u;                  // 200,000,000 < 2^31
    const unsigned s = blockIdx.x * SLICE;
    const unsigned e = (s + SLICE < n) ? (s + SLICE) : n;

    const unsigned bt0 = s / BT_STRIDE;              // const-div -> mul/shift
    const unsigned bt1 = (e - 1u) / BT_STRIDE;       // slice spans <=2 regions
    const unsigned nbt = bt1 - bt0 + 1u;             // 1 or 2

    const unsigned w = threadIdx.x >> 5;
    const unsigned l = threadIdx.x & 31u;

    bool     do_write = false;
    unsigned off      = 0;
    if (w < nbt && l < (unsigned)P) {
        const unsigned bt = bt0 + w;
        const float2 pt = __ldg(&x[bt * P + l]);     // (px, py)
        const float2 rs = __ldg(&resolution[bt]);
        const float2 og = __ldg(&origin[bt]);

        const int col = (int)(pt.x / rs.x + og.x);   // trunc == astype(int)
        const int row = (int)(pt.y / rs.y + og.y);

        if (row >= 0 && row < H && col >= 0 && col < W) {   // JAX drops OOB
            off = ((bt * (unsigned)H + (unsigned)row) * (unsigned)W
                       + (unsigned)col) * (unsigned)P + l;
            do_write = (off >= s && off < e);
        }
    }

    // ---- Phase 1: zero this block's slice (4x STG.128, evict-first) ----
    const float4 z = make_float4(0.f, 0.f, 0.f, 0.f);
    const unsigned base = blockIdx.x * (ZTHREADS * VPT) + threadIdx.x;
#pragma unroll
    for (int k = 0; k < VPT; k++) {
        unsigned i = base + k * ZTHREADS;
        if (i < n_vec4) {
            __stcs(reinterpret_cast<float4*>(out) + i, z);
        }
    }

    // CTA-scope ordering: this block's zeros precede its ones.
    __syncthreads();

    // ---- Phase 2b (post-barrier): single store, ~5cyc tail ----
    if (do_write) {
        out[off] = 1.0f;
    }
}

// ---------------------------------------------------------------------------
extern "C" void kernel_launch(void* const* d_in, const int* in_sizes, int n_in,
                              void* d_out, int out_size) {
    const float2* x          = (const float2*)d_in[0];
    const float2* resolution = (const float2*)d_in[1];
    const float2* origin     = (const float2*)d_in[2];
    float* out = (float*)d_out;

    const unsigned n = (unsigned)out_size;           // 200,000,000 (div by 4)
    const unsigned n_vec4 = n / 4u;                  // 50,000,000

    const unsigned slots = (n_vec4 + VPT - 1) / VPT;
    const unsigned blocks = (slots + ZTHREADS - 1) / ZTHREADS;   // 48829

    fused_raster_kernel<<<blocks, ZTHREADS>>>(x, resolution, origin, out, n_vec4);
}